// round 2
// baseline (speedup 1.0000x reference)
#include <cuda_runtime.h>
#include <cstdint>
#include <cstddef>

// ---------------- Problem constants ----------------
#define BB 64
#define SS 2048
#define DD 6
#define HH 8
#define NCHAIN (BB*HH)      // 512 independent scan chains
#define CS 32               // chunk size (steps per chunk)
#define NC (SS/CS)          // 64 chunks per chain
#define EPSN 1e-8f

// ---------------- Cl(4,1) sign (compile-time foldable) ----------------
__host__ __device__ constexpr int cpopc(unsigned v){ int c=0; while(v){ c += (int)(v&1u); v>>=1; } return c; }
__host__ __device__ constexpr float csign(int a, int b){
    int s = 0;
    int aa = a >> 1;
    while (aa){ s += cpopc((unsigned)(aa & b)); aa >>= 1; }
    if ((a & b) & 16) s++;              // e5*e5 = -1 (metric +,+,+,+,-)
    return (s & 1) ? -1.0f : 1.0f;
}

// ---------------- Scratch (device globals; no allocation) ----------------
__device__ static float g_delta[(size_t)NCHAIN * SS * 32];   // normalized deltas
__device__ static float g_T[(size_t)NCHAIN * NC * 32];       // chunk totals
__device__ static float g_E[(size_t)NCHAIN * NC * 32];       // exclusive chunk prefixes
__device__ static float g_psi[(size_t)BB * SS * HH * 32];    // psi_seq, layout (b,t,h,k)

// ======================================================================
// Kernel 0: delta[b,s,h,:] = normalize( (x[b,s,:] @ W_in + b_in)[h*32:..] + e0 )
// one warp per (bh, s); lane = component k
// ======================================================================
__global__ void k_delta(const float* __restrict__ x,
                        const float* __restrict__ W_in,
                        const float* __restrict__ b_in)
{
    const int lane = threadIdx.x & 31;
    const int gw = blockIdx.x * (blockDim.x >> 5) + (threadIdx.x >> 5);
    const int s  = gw & (SS - 1);
    const int bh = gw >> 11;                 // SS = 2048 = 2^11
    const int b  = bh >> 3;
    const int h  = bh & 7;

    const float* xp = x + ((size_t)b * SS + s) * DD;
    float u = __ldg(b_in + h*32 + lane);
#pragma unroll
    for (int d = 0; d < DD; d++)
        u = fmaf(__ldg(xp + d), __ldg(W_in + d*(HH*32) + h*32 + lane), u);
    if (lane == 0) u += 1.0f;

    float ss = u * u;
#pragma unroll
    for (int off = 16; off; off >>= 1) ss += __shfl_xor_sync(0xffffffffu, ss, off);
    const float inv = 1.0f / (sqrtf(ss) + EPSN);

    g_delta[((size_t)bh * SS + s) * 32 + lane] = u * inv;
}

// ---------------- in-register geometric product + normalize ----------------
__device__ __forceinline__ void gp_norm(const float d[32], float P[32])
{
    float Q[32];
#pragma unroll
    for (int k = 0; k < 32; k++) Q[k] = 0.0f;
#pragma unroll
    for (int i = 0; i < 32; i++){
        const float di = d[i];
#pragma unroll
        for (int k = 0; k < 32; k++){
            Q[k] = fmaf((csign(i, i ^ k) > 0.0f) ? di : -di, P[i ^ k], Q[k]);
        }
    }
    float s0 = 0.f, s1 = 0.f, s2 = 0.f, s3 = 0.f;
#pragma unroll
    for (int k = 0; k < 32; k += 4){
        s0 = fmaf(Q[k],   Q[k],   s0);
        s1 = fmaf(Q[k+1], Q[k+1], s1);
        s2 = fmaf(Q[k+2], Q[k+2], s2);
        s3 = fmaf(Q[k+3], Q[k+3], s3);
    }
    const float inv = 1.0f / (sqrtf((s0 + s1) + (s2 + s3)) + EPSN);
#pragma unroll
    for (int k = 0; k < 32; k++) P[k] = Q[k] * inv;
}

// ======================================================================
// Kernel 1: per-chunk total product (thread per chunk; 32 sequential GPs)
// ======================================================================
__global__ void k_chunk()
{
    const int idx = blockIdx.x * blockDim.x + threadIdx.x;   // [0, NCHAIN*NC)
    const int c  = idx & (NC - 1);
    const int bh = idx >> 6;

    const float4* dp = reinterpret_cast<const float4*>(g_delta + ((size_t)bh * SS + c * CS) * 32);

    float P[32];
#pragma unroll
    for (int k = 0; k < 32; k++) P[k] = 0.0f;
    P[0] = 1.0f;

    for (int s = 0; s < CS; s++){
        float d[32];
#pragma unroll
        for (int q = 0; q < 8; q++){
            float4 v = __ldg(dp + s*8 + q);
            d[4*q] = v.x; d[4*q+1] = v.y; d[4*q+2] = v.z; d[4*q+3] = v.w;
        }
        gp_norm(d, P);
    }

    float4* tp = reinterpret_cast<float4*>(g_T + (size_t)idx * 32);
#pragma unroll
    for (int q = 0; q < 8; q++)
        tp[q] = make_float4(P[4*q], P[4*q+1], P[4*q+2], P[4*q+3]);
}

// ======================================================================
// Kernel 2: sequential exclusive scan of chunk totals (warp per chain)
// E_0 = identity; E_{c+1} = N(T_c o E_c)
// ======================================================================
__global__ void k_scan()
{
    const int lane  = threadIdx.x & 31;
    const int chain = blockIdx.x * (blockDim.x >> 5) + (threadIdx.x >> 5);

    // per-lane sign row: sg[i] = csign(i, i^lane)
    float sg[32];
#pragma unroll
    for (int i = 0; i < 32; i++) sg[i] = csign(i, i ^ lane);

    float Ev = (lane == 0) ? 1.0f : 0.0f;
    g_E[((size_t)chain * NC + 0) * 32 + lane] = Ev;

    for (int c = 0; c < NC - 1; c++){
        const float Tv = g_T[((size_t)chain * NC + c) * 32 + lane];
        float acc = 0.0f;
#pragma unroll
        for (int i = 0; i < 32; i++){
            const float Ti = __shfl_sync(0xffffffffu, Tv, i);
            const float Pi = __shfl_xor_sync(0xffffffffu, Ev, i);
            acc = fmaf(sg[i] * Ti, Pi, acc);
        }
        float ss = acc * acc;
#pragma unroll
        for (int off = 16; off; off >>= 1) ss += __shfl_xor_sync(0xffffffffu, ss, off);
        Ev = acc / (sqrtf(ss) + EPSN);
        g_E[((size_t)chain * NC + c + 1) * 32 + lane] = Ev;
    }
}

// ======================================================================
// Kernel 3: re-run local prefixes seeded with E_c; emit normalized psi_t
// psi layout: ((b*S + t)*H + h)*32 + k  (rows of 256 for the projection)
// ======================================================================
__global__ void k_expand()
{
    const int idx = blockIdx.x * blockDim.x + threadIdx.x;   // [0, NCHAIN*NC)
    const int c  = idx & (NC - 1);
    const int bh = idx >> 6;
    const int b  = bh >> 3;
    const int h  = bh & 7;

    const float4* dp = reinterpret_cast<const float4*>(g_delta + ((size_t)bh * SS + c * CS) * 32);
    const float4* ep = reinterpret_cast<const float4*>(g_E + (size_t)idx * 32);

    float P[32];
#pragma unroll
    for (int q = 0; q < 8; q++){
        float4 v = __ldg(ep + q);
        P[4*q] = v.x; P[4*q+1] = v.y; P[4*q+2] = v.z; P[4*q+3] = v.w;
    }

    for (int s = 0; s < CS; s++){
        float d[32];
#pragma unroll
        for (int q = 0; q < 8; q++){
            float4 v = __ldg(dp + s*8 + q);
            d[4*q] = v.x; d[4*q+1] = v.y; d[4*q+2] = v.z; d[4*q+3] = v.w;
        }
        gp_norm(d, P);

        const int t = c * CS + s;
        float4* op = reinterpret_cast<float4*>(g_psi + (((size_t)b * SS + t) * HH + h) * 32);
#pragma unroll
        for (int q = 0; q < 8; q++)
            op[q] = make_float4(P[4*q], P[4*q+1], P[4*q+2], P[4*q+3]);
    }
}

// ======================================================================
// Kernel 4: out[b,t,:] = normalize( psi_row(256) @ W_out + b_out )
// thread computes 2 full rows (32 outputs each); W_out staged in smem
// ======================================================================
__global__ void k_proj(const float* __restrict__ W_out,
                       const float* __restrict__ b_out,
                       float* __restrict__ out)
{
    __shared__ float Wsm[256 * 32];
    __shared__ float bsm[32];

    const int tid = threadIdx.x;
    for (int i = tid; i < 256 * 32 / 4; i += blockDim.x)
        reinterpret_cast<float4*>(Wsm)[i] = __ldg(reinterpret_cast<const float4*>(W_out) + i);
    if (tid < 32) bsm[tid] = __ldg(b_out + tid);
    __syncthreads();

    const size_t row0 = ((size_t)blockIdx.x * blockDim.x + tid) * 2;
    const float4* a0 = reinterpret_cast<const float4*>(g_psi + row0 * 256);
    const float4* a1 = reinterpret_cast<const float4*>(g_psi + (row0 + 1) * 256);

    float acc0[32], acc1[32];
#pragma unroll
    for (int j = 0; j < 32; j++){ acc0[j] = 0.f; acc1[j] = 0.f; }

    for (int k4 = 0; k4 < 64; k4++){
        const float4 va = __ldg(a0 + k4);
        const float4 vb = __ldg(a1 + k4);
        const float av[4] = {va.x, va.y, va.z, va.w};
        const float bv[4] = {vb.x, vb.y, vb.z, vb.w};
#pragma unroll
        for (int t = 0; t < 4; t++){
            const int k = k4 * 4 + t;
            const float a = av[t];
            const float bvv = bv[t];
#pragma unroll
            for (int j4 = 0; j4 < 8; j4++){
                const float4 w = *reinterpret_cast<const float4*>(&Wsm[k * 32 + j4 * 4]);
                acc0[j4*4+0] = fmaf(a, w.x, acc0[j4*4+0]);
                acc0[j4*4+1] = fmaf(a, w.y, acc0[j4*4+1]);
                acc0[j4*4+2] = fmaf(a, w.z, acc0[j4*4+2]);
                acc0[j4*4+3] = fmaf(a, w.w, acc0[j4*4+3]);
                acc1[j4*4+0] = fmaf(bvv, w.x, acc1[j4*4+0]);
                acc1[j4*4+1] = fmaf(bvv, w.y, acc1[j4*4+1]);
                acc1[j4*4+2] = fmaf(bvv, w.z, acc1[j4*4+2]);
                acc1[j4*4+3] = fmaf(bvv, w.w, acc1[j4*4+3]);
            }
        }
    }

    // bias + normalize + store, per row
#pragma unroll
    for (int j = 0; j < 32; j++){ acc0[j] += bsm[j]; acc1[j] += bsm[j]; }

    float n0 = 0.f, n1 = 0.f;
#pragma unroll
    for (int j = 0; j < 32; j++){ n0 = fmaf(acc0[j], acc0[j], n0); n1 = fmaf(acc1[j], acc1[j], n1); }
    const float i0 = 1.0f / (sqrtf(n0) + EPSN);
    const float i1 = 1.0f / (sqrtf(n1) + EPSN);

    float4* o0 = reinterpret_cast<float4*>(out + row0 * 32);
    float4* o1 = reinterpret_cast<float4*>(out + (row0 + 1) * 32);
#pragma unroll
    for (int q = 0; q < 8; q++){
        o0[q] = make_float4(acc0[4*q]*i0, acc0[4*q+1]*i0, acc0[4*q+2]*i0, acc0[4*q+3]*i0);
        o1[q] = make_float4(acc1[4*q]*i1, acc1[4*q+1]*i1, acc1[4*q+2]*i1, acc1[4*q+3]*i1);
    }
}

// ======================================================================
extern "C" void kernel_launch(void* const* d_in, const int* in_sizes, int n_in,
                              void* d_out, int out_size)
{
    const float* x     = (const float*)d_in[0];
    const float* W_in  = (const float*)d_in[1];
    const float* b_in  = (const float*)d_in[2];
    const float* W_out = (const float*)d_in[3];
    const float* b_out = (const float*)d_in[4];
    float* out = (float*)d_out;

    // 0: deltas. one warp per (chain, s): NCHAIN*SS warps, 8 warps/block
    k_delta<<<(NCHAIN * SS) / 8, 256>>>(x, W_in, b_in);

    // 1: chunk totals. thread per (chain, chunk)
    k_chunk<<<(NCHAIN * NC) / 128, 128>>>();

    // 2: exclusive scan of chunk totals. warp per chain
    k_scan<<<NCHAIN / 8, 256>>>();

    // 3: expand prefixes, emit psi_seq
    k_expand<<<(NCHAIN * NC) / 128, 128>>>();

    // 4: output projection + normalize
    k_proj<<<(BB * SS / 2) / 256, 256>>>(W_out, b_out, out);
}

// round 3
// speedup vs baseline: 2.1303x; 2.1303x over previous
#include <cuda_runtime.h>
#include <cstdint>
#include <cstddef>

// ---------------- Problem constants ----------------
#define BB 64
#define SS 2048
#define DD 6
#define HH 8
#define NCHAIN (BB*HH)      // 512 independent scan chains
#define CS 16               // chunk size (steps per chunk)
#define NC (SS/CS)          // 128 chunks per chain
#define EPSN 1e-8f

// ---------------- Cl(4,1) sign (compile-time foldable) ----------------
__host__ __device__ constexpr int cpopc(unsigned v){ int c=0; while(v){ c += (int)(v&1u); v>>=1; } return c; }
__host__ __device__ constexpr float csign(int a, int b){
    int s = 0;
    int aa = a >> 1;
    while (aa){ s += cpopc((unsigned)(aa & b)); aa >>= 1; }
    if ((a & b) & 16) s++;              // e5*e5 = -1 (metric +,+,+,+,-)
    return (s & 1) ? -1.0f : 1.0f;
}

// ---------------- Scratch (device globals; no allocation) ----------------
__device__ static float g_delta[(size_t)NCHAIN * SS * 32];   // normalized deltas
__device__ static float g_T[(size_t)NCHAIN * NC * 32];       // chunk totals
__device__ static float g_E[(size_t)NCHAIN * NC * 32];       // exclusive chunk prefixes
__device__ static float g_psi[(size_t)BB * SS * HH * 32];    // psi_seq, layout (b,t,h,k)

// ======================================================================
// Kernel 0: delta[b,s,h,:] = normalize( (x[b,s,:] @ W_in + b_in)[h*32:..] + e0 )
// one warp per (b, s); loops over all 8 heads; lane = component k
// ======================================================================
__global__ void k_delta(const float* __restrict__ x,
                        const float* __restrict__ W_in,
                        const float* __restrict__ b_in)
{
    const int lane = threadIdx.x & 31;
    const int gw = blockIdx.x * (blockDim.x >> 5) + (threadIdx.x >> 5);  // [0, B*S)
    const int s  = gw & (SS - 1);
    const int b  = gw >> 11;                 // SS = 2048 = 2^11

    const float* xp = x + ((size_t)b * SS + s) * DD;
    float xv[DD];
#pragma unroll
    for (int d = 0; d < DD; d++) xv[d] = __ldg(xp + d);

#pragma unroll
    for (int h = 0; h < HH; h++){
        float u = __ldg(b_in + h*32 + lane);
#pragma unroll
        for (int d = 0; d < DD; d++)
            u = fmaf(xv[d], __ldg(W_in + d*(HH*32) + h*32 + lane), u);
        if (lane == 0) u += 1.0f;

        float ss = u * u;
#pragma unroll
        for (int off = 16; off; off >>= 1) ss += __shfl_xor_sync(0xffffffffu, ss, off);
        const float inv = 1.0f / (sqrtf(ss) + EPSN);

        g_delta[(((size_t)(b*HH + h)) * SS + s) * 32 + lane] = u * inv;
    }
}

// ---------------- in-register geometric product + normalize ----------------
// d streamed one float4 at a time -> live set ~ P[32]+Q[32]+4  (no spills)
__device__ __forceinline__ void gp_step(const float4* __restrict__ dp, float P[32])
{
    float Q[32];
#pragma unroll
    for (int k = 0; k < 32; k++) Q[k] = 0.0f;

#pragma unroll
    for (int q = 0; q < 8; q++){
        const float4 v = __ldg(dp + q);
#pragma unroll
        for (int t = 0; t < 4; t++){
            const int i = 4*q + t;
            const float dv = (t == 0) ? v.x : (t == 1) ? v.y : (t == 2) ? v.z : v.w;
#pragma unroll
            for (int k = 0; k < 32; k++){
                Q[k] = fmaf((csign(i, i ^ k) > 0.0f) ? dv : -dv, P[i ^ k], Q[k]);
            }
        }
    }

    float s0 = 0.f, s1 = 0.f, s2 = 0.f, s3 = 0.f;
#pragma unroll
    for (int k = 0; k < 32; k += 4){
        s0 = fmaf(Q[k],   Q[k],   s0);
        s1 = fmaf(Q[k+1], Q[k+1], s1);
        s2 = fmaf(Q[k+2], Q[k+2], s2);
        s3 = fmaf(Q[k+3], Q[k+3], s3);
    }
    const float inv = 1.0f / (sqrtf((s0 + s1) + (s2 + s3)) + EPSN);
#pragma unroll
    for (int k = 0; k < 32; k++) P[k] = Q[k] * inv;
}

// ======================================================================
// Kernel 1: per-chunk total product (thread per chunk; CS sequential GPs)
// ======================================================================
__global__ void __launch_bounds__(128) k_chunk()
{
    const int idx = blockIdx.x * blockDim.x + threadIdx.x;   // [0, NCHAIN*NC)
    const int c  = idx & (NC - 1);
    const int bh = idx >> 7;                                 // NC = 128 = 2^7

    const float4* dp = reinterpret_cast<const float4*>(g_delta + ((size_t)bh * SS + c * CS) * 32);

    float P[32];
#pragma unroll
    for (int k = 0; k < 32; k++) P[k] = 0.0f;
    P[0] = 1.0f;

    for (int s = 0; s < CS; s++)
        gp_step(dp + s*8, P);

    float4* tp = reinterpret_cast<float4*>(g_T + (size_t)idx * 32);
#pragma unroll
    for (int q = 0; q < 8; q++)
        tp[q] = make_float4(P[4*q], P[4*q+1], P[4*q+2], P[4*q+3]);
}

// ======================================================================
// Kernel 2: sequential exclusive scan of chunk totals (warp per chain)
// E_0 = identity; E_{c+1} = N(T_c o E_c)
// ======================================================================
__global__ void k_scan()
{
    const int lane  = threadIdx.x & 31;
    const int chain = blockIdx.x * (blockDim.x >> 5) + (threadIdx.x >> 5);

    // per-lane sign row: sg[i] = csign(i, i^lane)
    float sg[32];
#pragma unroll
    for (int i = 0; i < 32; i++) sg[i] = csign(i, i ^ lane);

    float Ev = (lane == 0) ? 1.0f : 0.0f;
    g_E[((size_t)chain * NC + 0) * 32 + lane] = Ev;

    for (int c = 0; c < NC - 1; c++){
        const float Tv = g_T[((size_t)chain * NC + c) * 32 + lane];
        float acc = 0.0f;
#pragma unroll
        for (int i = 0; i < 32; i++){
            const float Ti = __shfl_sync(0xffffffffu, Tv, i);
            const float Pi = __shfl_xor_sync(0xffffffffu, Ev, i);
            acc = fmaf(sg[i] * Ti, Pi, acc);
        }
        float ss = acc * acc;
#pragma unroll
        for (int off = 16; off; off >>= 1) ss += __shfl_xor_sync(0xffffffffu, ss, off);
        Ev = acc / (sqrtf(ss) + EPSN);
        g_E[((size_t)chain * NC + c + 1) * 32 + lane] = Ev;
    }
}

// ======================================================================
// Kernel 3: re-run local prefixes seeded with E_c; emit normalized psi_t
// psi layout: ((b*S + t)*H + h)*32 + k  (rows of 256 for the projection)
// ======================================================================
__global__ void __launch_bounds__(128) k_expand()
{
    const int idx = blockIdx.x * blockDim.x + threadIdx.x;   // [0, NCHAIN*NC)
    const int c  = idx & (NC - 1);
    const int bh = idx >> 7;
    const int b  = bh >> 3;
    const int h  = bh & 7;

    const float4* dp = reinterpret_cast<const float4*>(g_delta + ((size_t)bh * SS + c * CS) * 32);
    const float4* ep = reinterpret_cast<const float4*>(g_E + (size_t)idx * 32);

    float P[32];
#pragma unroll
    for (int q = 0; q < 8; q++){
        float4 v = __ldg(ep + q);
        P[4*q] = v.x; P[4*q+1] = v.y; P[4*q+2] = v.z; P[4*q+3] = v.w;
    }

    for (int s = 0; s < CS; s++){
        gp_step(dp + s*8, P);

        const int t = c * CS + s;
        float4* op = reinterpret_cast<float4*>(g_psi + (((size_t)b * SS + t) * HH + h) * 32);
#pragma unroll
        for (int q = 0; q < 8; q++)
            op[q] = make_float4(P[4*q], P[4*q+1], P[4*q+2], P[4*q+3]);
    }
}

// ======================================================================
// Kernel 4: out[b,t,:] = normalize( psi_row(256) @ W_out + b_out )
// thread computes 1 full row (32 outputs); W_out staged in smem
// ======================================================================
__global__ void __launch_bounds__(256) k_proj(const float* __restrict__ W_out,
                                              const float* __restrict__ b_out,
                                              float* __restrict__ out)
{
    __shared__ float Wsm[256 * 32];
    __shared__ float bsm[32];

    const int tid = threadIdx.x;
    for (int i = tid; i < 256 * 32 / 4; i += blockDim.x)
        reinterpret_cast<float4*>(Wsm)[i] = __ldg(reinterpret_cast<const float4*>(W_out) + i);
    if (tid < 32) bsm[tid] = __ldg(b_out + tid);
    __syncthreads();

    const size_t row = (size_t)blockIdx.x * blockDim.x + tid;
    const float4* a0 = reinterpret_cast<const float4*>(g_psi + row * 256);

    float acc[32];
#pragma unroll
    for (int j = 0; j < 32; j++) acc[j] = 0.f;

    for (int k4 = 0; k4 < 64; k4++){
        const float4 va = __ldg(a0 + k4);
#pragma unroll
        for (int t = 0; t < 4; t++){
            const int k = k4 * 4 + t;
            const float a = (t == 0) ? va.x : (t == 1) ? va.y : (t == 2) ? va.z : va.w;
#pragma unroll
            for (int j4 = 0; j4 < 8; j4++){
                const float4 w = *reinterpret_cast<const float4*>(&Wsm[k * 32 + j4 * 4]);
                acc[j4*4+0] = fmaf(a, w.x, acc[j4*4+0]);
                acc[j4*4+1] = fmaf(a, w.y, acc[j4*4+1]);
                acc[j4*4+2] = fmaf(a, w.z, acc[j4*4+2]);
                acc[j4*4+3] = fmaf(a, w.w, acc[j4*4+3]);
            }
        }
    }

#pragma unroll
    for (int j = 0; j < 32; j++) acc[j] += bsm[j];

    float n0 = 0.f;
#pragma unroll
    for (int j = 0; j < 32; j++) n0 = fmaf(acc[j], acc[j], n0);
    const float i0 = 1.0f / (sqrtf(n0) + EPSN);

    float4* o0 = reinterpret_cast<float4*>(out + row * 32);
#pragma unroll
    for (int q = 0; q < 8; q++)
        o0[q] = make_float4(acc[4*q]*i0, acc[4*q+1]*i0, acc[4*q+2]*i0, acc[4*q+3]*i0);
}

// ======================================================================
extern "C" void kernel_launch(void* const* d_in, const int* in_sizes, int n_in,
                              void* d_out, int out_size)
{
    const float* x     = (const float*)d_in[0];
    const float* W_in  = (const float*)d_in[1];
    const float* b_in  = (const float*)d_in[2];
    const float* W_out = (const float*)d_in[3];
    const float* b_out = (const float*)d_in[4];
    float* out = (float*)d_out;

    // 0: deltas. one warp per (b, s): B*S warps, 8 warps/block
    k_delta<<<(BB * SS) / 8, 256>>>(x, W_in, b_in);

    // 1: chunk totals. thread per (chain, chunk)
    k_chunk<<<(NCHAIN * NC) / 128, 128>>>();

    // 2: exclusive scan of chunk totals. warp per chain
    k_scan<<<NCHAIN / 8, 256>>>();

    // 3: expand prefixes, emit psi_seq
    k_expand<<<(NCHAIN * NC) / 128, 128>>>();

    // 4: output projection + normalize
    k_proj<<<(BB * SS) / 256, 256>>>(W_out, b_out, out);
}